// round 3
// baseline (speedup 1.0000x reference)
#include <cuda_runtime.h>
#include <cuda_fp16.h>
#include <math.h>

#define NB 8
#define NC 32
#define NR 2048
#define NI 64
#define NO 64

// Scratch (static device globals — no allocation in kernel_launch)
__device__ __half g_ph[NB * NC * NR * NO];      // 67 MB fp16 priors -> L2 resident
__device__ float  g_w[NB * NC * NO];            // cumulative v (logit weight)
__device__ float  g_pden[2 * NB * NC * NO];     // per-half softmax denominators
__device__ float  g_pnum[2 * NB * NC * NO];     // per-half softmax numerators

// ---------------------------------------------------------------------------
// Kernel 1: priors[b,c,r,o] = sum_i x[b,c,r,i] * W[c,r,i,o], stored as fp16.
// Round-1 load structure (plain loads — 6.2 TB/s measured), fp16 store.
// ---------------------------------------------------------------------------
__global__ __launch_bounds__(128) void priors_kernel(
    const float* __restrict__ x, const float* __restrict__ Wt)
{
    const int c  = blockIdx.y;
    const int r0 = blockIdx.x * 8;
    const int t  = threadIdx.x;

    if (blockIdx.x == 0 && blockIdx.y == 0) {
        for (int q = t; q < NB * NC * NO; q += 128) g_w[q] = 0.0f;
    }

    __shared__ float sX[NB * 8 * NI];   // [b][rj][i], 16 KB
    {
        const float4* x4 = (const float4*)x;
        float4* sX4 = (float4*)sX;
#pragma unroll
        for (int q = 0; q < 8; q++) {
            int idx = t + 128 * q;          // 0..1023 float4s
            int b   = idx >> 7;
            int rem = idx & 127;
            int rj  = rem >> 4;
            int f   = rem & 15;
            sX4[(b * 8 + rj) * 16 + f] =
                x4[((size_t)((b * NC + c) * NR + r0 + rj)) * 16 + f];
        }
    }
    __syncthreads();

    const int rj = t >> 4;
    const int og = t & 15;
    const int r  = r0 + rj;
    const float4* w4p = (const float4*)(Wt + (size_t)(c * NR + r) * (NI * NO));

    float4 acc[NB];
#pragma unroll
    for (int b = 0; b < NB; b++) acc[b] = make_float4(0.f, 0.f, 0.f, 0.f);

#pragma unroll 4
    for (int i = 0; i < NI; i++) {
        float4 w = w4p[i * 16 + og];
#pragma unroll
        for (int b = 0; b < NB; b++) {
            float xv = sX[(b * 8 + rj) * NI + i];
            acc[b].x += xv * w.x;
            acc[b].y += xv * w.y;
            acc[b].z += xv * w.z;
            acc[b].w += xv * w.w;
        }
    }

#pragma unroll
    for (int b = 0; b < NB; b++) {
        union { uint2 u; __half2 h[2]; } pk;
        pk.h[0] = __floats2half2_rn(acc[b].x, acc[b].y);
        pk.h[1] = __floats2half2_rn(acc[b].z, acc[b].w);
        *(uint2*)(g_ph + (size_t)((b * NC + c) * NR + r) * NO + 4 * og) = pk.u;
    }
}

// ---------------------------------------------------------------------------
// Kernel 2: one routing iteration (no max needed: |w|<=2, |p|<=~16 so
// |logit| <= ~32, exp() safe in fp32; denominator well-conditioned).
// Grid = 512: 2 blocks per (b,c), each handles 1024 rows; partial num/den
// go to scratch, combined in squash.
// ---------------------------------------------------------------------------
__global__ __launch_bounds__(512) void iter_kernel()
{
    const int blk  = blockIdx.x;
    const int bc   = blk >> 1;
    const int half = blk & 1;
    const int t    = threadIdx.x;
    const int o4   = t & 15;            // half4 index over o
    const int g    = t >> 4;            // 0..31 row-lane

    const uint2* p2 = (const uint2*)(g_ph + (size_t)bc * NR * NO)
                      + (size_t)half * 1024 * 16;
    const float4 wv = ((const float4*)g_w)[bc * 16 + o4];

    float d0 = 0.f, d1 = 0.f, d2 = 0.f, d3 = 0.f;
    float n0 = 0.f, n1 = 0.f, n2 = 0.f, n3 = 0.f;

#pragma unroll 8
    for (int k = 0; k < 32; k++) {
        uint2 u = p2[(size_t)(g + 32 * k) * 16 + o4];
        float2 pa = __half22float2(*(__half2*)&u.x);
        float2 pb = __half22float2(*(__half2*)&u.y);
        float e;
        e = __expf(pa.x * wv.x); d0 += e; n0 += pa.x * e;
        e = __expf(pa.y * wv.y); d1 += e; n1 += pa.y * e;
        e = __expf(pb.x * wv.z); d2 += e; n2 += pb.x * e;
        e = __expf(pb.y * wv.w); d3 += e; n3 += pb.y * e;
    }

    __shared__ float sm[2][32][64];     // den / num, 16 KB
    {
        int ob = o4 * 4;
        sm[0][g][ob + 0] = d0; sm[1][g][ob + 0] = n0;
        sm[0][g][ob + 1] = d1; sm[1][g][ob + 1] = n1;
        sm[0][g][ob + 2] = d2; sm[1][g][ob + 2] = n2;
        sm[0][g][ob + 3] = d3; sm[1][g][ob + 3] = n3;
    }
    __syncthreads();

    if (t < 64) {
        float D = 0.f, N = 0.f;
#pragma unroll 8
        for (int g2 = 0; g2 < 32; g2++) {
            D += sm[0][g2][t];
            N += sm[1][g2][t];
        }
        g_pden[half * (NB * NC * NO) + bc * NO + t] = D;
        g_pnum[half * (NB * NC * NO) + bc * NO + t] = N;
    }
}

// ---------------------------------------------------------------------------
// Kernel 3: combine partials -> s, global squash scale, update w or write out.
// ---------------------------------------------------------------------------
__global__ __launch_bounds__(512) void squash_kernel(float* __restrict__ out, int last)
{
    const int t = threadIdx.x;
    const int TOT = NB * NC * NO;       // 16384

    float sv[32];
    float acc = 0.f;
#pragma unroll
    for (int q = 0; q < 32; q++) {
        int j = t + 512 * q;
        float D = g_pden[j] + g_pden[TOT + j];
        float N = g_pnum[j] + g_pnum[TOT + j];
        float s = N / D;
        sv[q] = s;
        acc += s * s;
    }

    __shared__ float red[16];
    __shared__ float s_scale;
#pragma unroll
    for (int off = 16; off > 0; off >>= 1)
        acc += __shfl_xor_sync(0xFFFFFFFFu, acc, off);
    if ((t & 31) == 0) red[t >> 5] = acc;
    __syncthreads();
    if (t < 32) {
        float a = (t < 16) ? red[t] : 0.f;
#pragma unroll
        for (int off = 8; off > 0; off >>= 1)
            a += __shfl_xor_sync(0xFFFFFFFFu, a, off);
        if (t == 0) s_scale = sqrtf(a) / (1.0f + a);
    }
    __syncthreads();
    const float sc = s_scale;

    if (last) {
#pragma unroll
        for (int q = 0; q < 32; q++) out[t + 512 * q] = sv[q] * sc;
    } else {
#pragma unroll
        for (int q = 0; q < 32; q++) g_w[t + 512 * q] += sv[q] * sc;
    }
}

// ---------------------------------------------------------------------------
extern "C" void kernel_launch(void* const* d_in, const int* in_sizes, int n_in,
                              void* d_out, int out_size)
{
    (void)in_sizes; (void)n_in; (void)out_size;
    const float* x  = (const float*)d_in[0];
    const float* Wt = (const float*)d_in[1];
    float* out = (float*)d_out;

    priors_kernel<<<dim3(NR / 8, NC), 128>>>(x, Wt);

    iter_kernel<<<2 * NB * NC, 512>>>();
    squash_kernel<<<1, 512>>>(nullptr, 0);      // w = v0

    iter_kernel<<<2 * NB * NC, 512>>>();
    squash_kernel<<<1, 512>>>(nullptr, 0);      // w = v0 + v1

    iter_kernel<<<2 * NB * NC, 512>>>();
    squash_kernel<<<1, 512>>>(out, 1);
}

// round 5
// speedup vs baseline: 1.0574x; 1.0574x over previous
#include <cuda_runtime.h>
#include <cuda_fp16.h>
#include <cstdint>
#include <math.h>

#define NB 8
#define NC 32
#define NR 2048
#define NI 64
#define NO 64
#define RT 16        // r-values per priors block

// Scratch (static device globals — no allocation in kernel_launch)
__device__ __half g_ph[NB * NC * NR * NO];      // 67 MB fp16 priors -> L2 resident
__device__ float  g_w[NB * NC * NO];            // cumulative v (logit weight)
__device__ float  g_pden[2 * NB * NC * NO];     // per-half softmax denominators
__device__ float  g_pnum[2 * NB * NC * NO];     // per-half numerators; [0] also = sum_r priors

// ---------------------------------------------------------------------------
__device__ __forceinline__ void cpa16(void* dst, const void* src) {
    unsigned s = (unsigned)__cvta_generic_to_shared(dst);
    asm volatile("cp.async.cg.shared.global [%0], [%1], 16;" :: "r"(s), "l"(src));
}
__device__ __forceinline__ void cpa_commit() {
    asm volatile("cp.async.commit_group;");
}
__device__ __forceinline__ void cpa_wait1() {
    asm volatile("cp.async.wait_group 1;");
}

// ---------------------------------------------------------------------------
// Kernel 0: zero the accumulators.
// ---------------------------------------------------------------------------
__global__ __launch_bounds__(512) void zero_kernel()
{
    int i = blockIdx.x * 512 + threadIdx.x;
    if (i < NB * NC * NO) g_w[i] = 0.0f;
    if (i < 2 * NB * NC * NO) g_pnum[i] = 0.0f;
}

// ---------------------------------------------------------------------------
// Kernel 1: priors[b,c,r,o] = sum_i x[b,c,r,i] * W[c,r,i,o], fp16 store.
// cp.async double-buffered pipeline over r: per stage 16KB W + 2KB x land in
// smem while the previous stage computes -> DRAM stays saturated.
// Also accumulates sum_r priors (iteration-0 fusion) via atomicAdd.
// Block: 128 threads = (b = t/16) x (og = t%16, 4 outputs each), (c, 16 r).
// ---------------------------------------------------------------------------
__global__ __launch_bounds__(128) void priors_kernel(
    const float* __restrict__ x, const float* __restrict__ Wt)
{
    __shared__ float sW[2][NI * NO];    // 2 x 16KB
    __shared__ float sX[2][NB * NI];    // 2 x 2KB   [b][i]

    const int c  = blockIdx.y;
    const int r0 = blockIdx.x * RT;
    const int t  = threadIdx.x;
    const int b  = t >> 4;
    const int og = t & 15;

    const float4* x4 = (const float4*)x;

    // stage loader: W slab (1024 float4, 8/thread) + x rows (1 float4/thread)
    auto load_stage = [&](int rr, int s) {
        const float4* wsrc = (const float4*)(Wt + (size_t)(c * NR + r0 + rr) * (NI * NO));
        float4* wdst = (float4*)sW[s];
#pragma unroll
        for (int q = 0; q < 8; q++)
            cpa16(wdst + t + 128 * q, wsrc + t + 128 * q);
        int lb = t >> 4, f = t & 15;
        cpa16(((float4*)sX[s]) + t,
              x4 + (size_t)((lb * NC + c) * NR + r0 + rr) * 16 + f);
        cpa_commit();
    };

    load_stage(0, 0);

    float4 msum = make_float4(0.f, 0.f, 0.f, 0.f);

    for (int rr = 0; rr < RT; rr++) {
        if (rr + 1 < RT) load_stage(rr + 1, (rr + 1) & 1);
        else             cpa_commit();          // dummy group keeps accounting uniform
        cpa_wait1();                            // stage rr (this thread) complete
        __syncthreads();                        // stage rr complete block-wide

        const float* Wrow = sW[rr & 1];
        const float* xr   = sX[rr & 1] + b * NI;

        float4 acc = make_float4(0.f, 0.f, 0.f, 0.f);
#pragma unroll 16
        for (int i = 0; i < NI; i++) {
            float4 w = *(const float4*)(Wrow + i * NO + og * 4);
            float xv = xr[i];
            acc.x += xv * w.x;
            acc.y += xv * w.y;
            acc.z += xv * w.z;
            acc.w += xv * w.w;
        }

        // fp16 store of this (b, r, 4 o's)
        union { uint2 u; __half2 h[2]; } pk;
        pk.h[0] = __floats2half2_rn(acc.x, acc.y);
        pk.h[1] = __floats2half2_rn(acc.z, acc.w);
        *(uint2*)(g_ph + (size_t)((b * NC + c) * NR + r0 + rr) * NO + 4 * og) = pk.u;

        msum.x += acc.x; msum.y += acc.y; msum.z += acc.z; msum.w += acc.w;

        __syncthreads();                        // stage rr free for reuse
    }

    // iteration-0 fusion: sum_r priors -> g_pnum[0]
    float* dst = g_pnum + (b * NC + c) * NO + og * 4;
    atomicAdd(dst + 0, msum.x);
    atomicAdd(dst + 1, msum.y);
    atomicAdd(dst + 2, msum.z);
    atomicAdd(dst + 3, msum.w);
}

// ---------------------------------------------------------------------------
// Kernel 2: one routing iteration (branch-free: |w|<=2, |p|<~16 -> exp safe).
// Grid = 512: 2 blocks per (b,c); partial num/den to scratch halves.
// ---------------------------------------------------------------------------
__global__ __launch_bounds__(512) void iter_kernel()
{
    const int blk  = blockIdx.x;
    const int bc   = blk >> 1;
    const int half = blk & 1;
    const int t    = threadIdx.x;
    const int o4   = t & 15;
    const int g    = t >> 4;

    const uint2* p2 = (const uint2*)(g_ph + (size_t)bc * NR * NO)
                      + (size_t)half * 1024 * 16;
    const float4 wv = ((const float4*)g_w)[bc * 16 + o4];

    float d0 = 0.f, d1 = 0.f, d2 = 0.f, d3 = 0.f;
    float n0 = 0.f, n1 = 0.f, n2 = 0.f, n3 = 0.f;

#pragma unroll 8
    for (int k = 0; k < 32; k++) {
        uint2 u = p2[(size_t)(g + 32 * k) * 16 + o4];
        float2 pa = __half22float2(*(__half2*)&u.x);
        float2 pb = __half22float2(*(__half2*)&u.y);
        float e;
        e = __expf(pa.x * wv.x); d0 += e; n0 += pa.x * e;
        e = __expf(pa.y * wv.y); d1 += e; n1 += pa.y * e;
        e = __expf(pb.x * wv.z); d2 += e; n2 += pb.x * e;
        e = __expf(pb.y * wv.w); d3 += e; n3 += pb.y * e;
    }

    __shared__ float sm[2][32][64];
    {
        int ob = o4 * 4;
        sm[0][g][ob + 0] = d0; sm[1][g][ob + 0] = n0;
        sm[0][g][ob + 1] = d1; sm[1][g][ob + 1] = n1;
        sm[0][g][ob + 2] = d2; sm[1][g][ob + 2] = n2;
        sm[0][g][ob + 3] = d3; sm[1][g][ob + 3] = n3;
    }
    __syncthreads();

    if (t < 64) {
        float D = 0.f, N = 0.f;
#pragma unroll 8
        for (int g2 = 0; g2 < 32; g2++) {
            D += sm[0][g2][t];
            N += sm[1][g2][t];
        }
        g_pden[half * (NB * NC * NO) + bc * NO + t] = D;
        g_pnum[half * (NB * NC * NO) + bc * NO + t] = N;
    }
}

// ---------------------------------------------------------------------------
// Kernel 3: s -> squash scale -> update w or write out.
// first=1: s = g_pnum[0]/2048 (uniform softmax, fused iteration 0).
// ---------------------------------------------------------------------------
__global__ __launch_bounds__(512) void squash_kernel(float* __restrict__ out,
                                                     int last, int first)
{
    const int t = threadIdx.x;
    const int TOT = NB * NC * NO;

    float sv[32];
    float acc = 0.f;
#pragma unroll
    for (int q = 0; q < 32; q++) {
        int j = t + 512 * q;
        float s;
        if (first) {
            s = g_pnum[j] * (1.0f / (float)NR);
        } else {
            float D = g_pden[j] + g_pden[TOT + j];
            float N = g_pnum[j] + g_pnum[TOT + j];
            s = N / D;
        }
        sv[q] = s;
        acc += s * s;
    }

    __shared__ float red[16];
    __shared__ float s_scale;
#pragma unroll
    for (int off = 16; off > 0; off >>= 1)
        acc += __shfl_xor_sync(0xFFFFFFFFu, acc, off);
    if ((t & 31) == 0) red[t >> 5] = acc;
    __syncthreads();
    if (t < 32) {
        float a = (t < 16) ? red[t] : 0.f;
#pragma unroll
        for (int off = 8; off > 0; off >>= 1)
            a += __shfl_xor_sync(0xFFFFFFFFu, a, off);
        if (t == 0) s_scale = sqrtf(a) / (1.0f + a);
    }
    __syncthreads();
    const float sc = s_scale;

    if (last) {
#pragma unroll
        for (int q = 0; q < 32; q++) out[t + 512 * q] = sv[q] * sc;
    } else {
#pragma unroll
        for (int q = 0; q < 32; q++) g_w[t + 512 * q] += sv[q] * sc;
    }
}

// ---------------------------------------------------------------------------
extern "C" void kernel_launch(void* const* d_in, const int* in_sizes, int n_in,
                              void* d_out, int out_size)
{
    (void)in_sizes; (void)n_in; (void)out_size;
    const float* x  = (const float*)d_in[0];
    const float* Wt = (const float*)d_in[1];
    float* out = (float*)d_out;

    zero_kernel<<<64, 512>>>();
    priors_kernel<<<dim3(NR / RT, NC), 128>>>(x, Wt);   // also fuses iteration 0 sum

    squash_kernel<<<1, 512>>>(nullptr, 0, 1);   // w = v0   (iteration 0)

    iter_kernel<<<2 * NB * NC, 512>>>();        // iteration 1
    squash_kernel<<<1, 512>>>(nullptr, 0, 0);   // w = v0 + v1

    iter_kernel<<<2 * NB * NC, 512>>>();        // iteration 2
    squash_kernel<<<1, 512>>>(out, 1, 0);       // final squash -> output
}

// round 7
// speedup vs baseline: 1.2257x; 1.1591x over previous
#include <cuda_runtime.h>
#include <cuda_fp16.h>
#include <cstdint>
#include <math.h>

#define NB 8
#define NC 32
#define NR 2048
#define NI 64
#define NO 64
#define RT 16                 // r-values per priors block
#define RS 2                  // r-values per pipeline stage (32 KB W slab)
#define NSTAGE (RT / RS)      // 8

// dynamic smem layout (bytes)
#define SMEM_W     0          // 2 x RS*NI*NO floats = 2 x 32768 B
#define SMEM_X     65536      // NB*RT*NI floats     = 32768 B
#define SMEM_MBAR  98304      // 2 mbarriers
#define SMEM_TOTAL 98432

// Scratch (static device globals — no allocation in kernel_launch)
__device__ __half g_ph[NB * NC * NR * NO];      // 67 MB fp16 priors -> L2 resident
__device__ float  g_w[NB * NC * NO];            // cumulative v (logit weight)
__device__ float  g_pden[2 * NB * NC * NO];     // per-half softmax denominators
__device__ float  g_pnum[2 * NB * NC * NO];     // per-half numerators; [0] also = sum_r priors

// ---------------------------------------------------------------------------
__device__ __forceinline__ unsigned sptr(const void* p) {
    return (unsigned)__cvta_generic_to_shared(p);
}
__device__ __forceinline__ void mbar_init(unsigned m, unsigned cnt) {
    asm volatile("mbarrier.init.shared.b64 [%0], %1;" :: "r"(m), "r"(cnt) : "memory");
}
__device__ __forceinline__ void mbar_expect(unsigned m, unsigned bytes) {
    asm volatile("mbarrier.arrive.expect_tx.shared.b64 _, [%0], %1;"
                 :: "r"(m), "r"(bytes) : "memory");
}
__device__ __forceinline__ void bulk_g2s(unsigned dst, const void* src,
                                         unsigned bytes, unsigned m) {
    asm volatile("cp.async.bulk.shared::cta.global.mbarrier::complete_tx::bytes "
                 "[%0], [%1], %2, [%3];"
                 :: "r"(dst), "l"(src), "r"(bytes), "r"(m) : "memory");
}
__device__ __forceinline__ void mbar_wait(unsigned m, unsigned ph) {
    asm volatile(
        "{\n\t.reg .pred P;\n\t"
        "W1_%=:\n\t"
        "mbarrier.try_wait.parity.acquire.cta.shared::cta.b64 P, [%0], %1, 0x989680;\n\t"
        "@P bra W2_%=;\n\t"
        "bra W1_%=;\n\t"
        "W2_%=:\n\t}"
        :: "r"(m), "r"(ph) : "memory");
}

#define FMA4(A, S, W) { (A).x += (S)*(W).x; (A).y += (S)*(W).y; \
                        (A).z += (S)*(W).z; (A).w += (S)*(W).w; }

// ---------------------------------------------------------------------------
// Kernel 0: zero the accumulators.
// ---------------------------------------------------------------------------
__global__ __launch_bounds__(512) void zero_kernel()
{
    int i = blockIdx.x * 512 + threadIdx.x;
    if (i < NB * NC * NO) g_w[i] = 0.0f;
    if (i < 2 * NB * NC * NO) g_pnum[i] = 0.0f;
}

// ---------------------------------------------------------------------------
// Kernel 1: priors[b,c,r,o] = sum_i x[b,c,r,i] * W[c,r,i,o], fp16 store.
// TMA bulk double-buffered pipeline: one 32 KB cp.async.bulk per stage (2 r's
// of W, contiguous), x slab (8 x 4 KB) loaded once. Fuses iteration-0 sum.
// Block: 128 threads = (rj 0..1) x (bq 0..3) x (og 0..15); thread computes
// 2 batches (2bq, 2bq+1) x 4 outputs for r = r0 + 2s + rj.
// ---------------------------------------------------------------------------
__global__ __launch_bounds__(128) void priors_kernel(
    const float* __restrict__ x, const float* __restrict__ Wt)
{
    extern __shared__ float sm[];
    float* sW = sm;                          // [2][RS*NI*NO]
    float* sX = sm + SMEM_X / 4;             // [NB][RT*NI]
    const unsigned smb = sptr(sm);
    const unsigned mb0 = smb + SMEM_MBAR;
    const unsigned mb1 = mb0 + 8;

    const int c  = blockIdx.y;
    const int r0 = blockIdx.x * RT;
    const int t  = threadIdx.x;
    const int rj = t >> 6;
    const int bq = (t >> 4) & 3;
    const int og = t & 15;
    const int b0 = 2 * bq, b1 = 2 * bq + 1;

    if (t == 0) { mbar_init(mb0, 1); mbar_init(mb1, 1); }
    __syncthreads();

    // stage 0: W slab + full x slab on mbar0
    if (t == 0) {
        mbar_expect(mb0, 32768 + NB * RT * NI * 4);
        bulk_g2s(smb + SMEM_W, Wt + (size_t)(c * NR + r0) * (NI * NO), 32768, mb0);
#pragma unroll
        for (int b = 0; b < NB; b++)
            bulk_g2s(smb + SMEM_X + b * (RT * NI * 4),
                     x + (size_t)((b * NC + c) * NR + r0) * NI,
                     RT * NI * 4, mb0);
    }

    unsigned ph0 = 0, ph1 = 0;
    float4 ms0 = make_float4(0.f, 0.f, 0.f, 0.f);
    float4 ms1 = make_float4(0.f, 0.f, 0.f, 0.f);

    for (int s = 0; s < NSTAGE; s++) {
        const int buf = s & 1;

        // prefetch next stage's W (buffer freed by the syncthreads at s-1 end)
        if (t == 0 && s + 1 < NSTAGE) {
            unsigned m2 = (s + 1) & 1 ? mb1 : mb0;
            mbar_expect(m2, 32768);
            bulk_g2s(smb + SMEM_W + ((s + 1) & 1) * 32768,
                     Wt + (size_t)(c * NR + r0 + (s + 1) * RS) * (NI * NO),
                     32768, m2);
        }

        if (buf == 0) { mbar_wait(mb0, ph0); ph0 ^= 1; }
        else          { mbar_wait(mb1, ph1); ph1 ^= 1; }

        const int rloc = s * RS + rj;
        const float*  Wb  = sW + buf * (RS * NI * NO) + rj * (NI * NO);
        const float4* xr0 = (const float4*)(sX + (b0 * RT + rloc) * NI);
        const float4* xr1 = (const float4*)(sX + (b1 * RT + rloc) * NI);

        float4 a0 = make_float4(0.f, 0.f, 0.f, 0.f);
        float4 a1 = make_float4(0.f, 0.f, 0.f, 0.f);

#pragma unroll
        for (int i4 = 0; i4 < NI / 4; i4++) {
            float4 xv0 = xr0[i4];
            float4 xv1 = xr1[i4];
            const float4* wrow = (const float4*)(Wb + (i4 * 4) * NO) + og;
            float4 w0 = wrow[0];
            float4 w1 = wrow[16];
            float4 w2 = wrow[32];
            float4 w3 = wrow[48];
            FMA4(a0, xv0.x, w0); FMA4(a1, xv1.x, w0);
            FMA4(a0, xv0.y, w1); FMA4(a1, xv1.y, w1);
            FMA4(a0, xv0.z, w2); FMA4(a1, xv1.z, w2);
            FMA4(a0, xv0.w, w3); FMA4(a1, xv1.w, w3);
        }

        // fp16 stores
        {
            union { uint2 u; __half2 h[2]; } pk;
            pk.h[0] = __floats2half2_rn(a0.x, a0.y);
            pk.h[1] = __floats2half2_rn(a0.z, a0.w);
            *(uint2*)(g_ph + (size_t)((b0 * NC + c) * NR + r0 + rloc) * NO + 4 * og) = pk.u;
            pk.h[0] = __floats2half2_rn(a1.x, a1.y);
            pk.h[1] = __floats2half2_rn(a1.z, a1.w);
            *(uint2*)(g_ph + (size_t)((b1 * NC + c) * NR + r0 + rloc) * NO + 4 * og) = pk.u;
        }

        ms0.x += a0.x; ms0.y += a0.y; ms0.z += a0.z; ms0.w += a0.w;
        ms1.x += a1.x; ms1.y += a1.y; ms1.z += a1.z; ms1.w += a1.w;

        __syncthreads();     // stage buffer free for reuse
    }

    // iteration-0 fusion: sum_r priors -> g_pnum[0..]
    float* d0 = g_pnum + (b0 * NC + c) * NO + 4 * og;
    float* d1 = g_pnum + (b1 * NC + c) * NO + 4 * og;
    atomicAdd(d0 + 0, ms0.x); atomicAdd(d0 + 1, ms0.y);
    atomicAdd(d0 + 2, ms0.z); atomicAdd(d0 + 3, ms0.w);
    atomicAdd(d1 + 0, ms1.x); atomicAdd(d1 + 1, ms1.y);
    atomicAdd(d1 + 2, ms1.z); atomicAdd(d1 + 3, ms1.w);
}

// ---------------------------------------------------------------------------
// Kernel 2: one routing iteration (branch-free: |w|<=2, |p|<~16 -> exp safe).
// Grid = 512: 2 blocks per (b,c); partial num/den to scratch halves.
// ---------------------------------------------------------------------------
__global__ __launch_bounds__(512) void iter_kernel()
{
    const int blk  = blockIdx.x;
    const int bc   = blk >> 1;
    const int half = blk & 1;
    const int t    = threadIdx.x;
    const int o4   = t & 15;
    const int g    = t >> 4;

    const uint2* p2 = (const uint2*)(g_ph + (size_t)bc * NR * NO)
                      + (size_t)half * 1024 * 16;
    const float4 wv = ((const float4*)g_w)[bc * 16 + o4];

    float d0 = 0.f, d1 = 0.f, d2 = 0.f, d3 = 0.f;
    float n0 = 0.f, n1 = 0.f, n2 = 0.f, n3 = 0.f;

#pragma unroll 8
    for (int k = 0; k < 32; k++) {
        uint2 u = p2[(size_t)(g + 32 * k) * 16 + o4];
        float2 pa = __half22float2(*(__half2*)&u.x);
        float2 pb = __half22float2(*(__half2*)&u.y);
        float e;
        e = __expf(pa.x * wv.x); d0 += e; n0 += pa.x * e;
        e = __expf(pa.y * wv.y); d1 += e; n1 += pa.y * e;
        e = __expf(pb.x * wv.z); d2 += e; n2 += pb.x * e;
        e = __expf(pb.y * wv.w); d3 += e; n3 += pb.y * e;
    }

    __shared__ float smr[2][32][64];
    {
        int ob = o4 * 4;
        smr[0][g][ob + 0] = d0; smr[1][g][ob + 0] = n0;
        smr[0][g][ob + 1] = d1; smr[1][g][ob + 1] = n1;
        smr[0][g][ob + 2] = d2; smr[1][g][ob + 2] = n2;
        smr[0][g][ob + 3] = d3; smr[1][g][ob + 3] = n3;
    }
    __syncthreads();

    if (t < 64) {
        float D = 0.f, N = 0.f;
#pragma unroll 8
        for (int g2 = 0; g2 < 32; g2++) {
            D += smr[0][g2][t];
            N += smr[1][g2][t];
        }
        g_pden[half * (NB * NC * NO) + bc * NO + t] = D;
        g_pnum[half * (NB * NC * NO) + bc * NO + t] = N;
    }
}

// ---------------------------------------------------------------------------
// Kernel 3: s -> squash scale -> update w or write out.
// first=1: s = g_pnum[0]/2048 (uniform softmax, fused iteration 0).
// ---------------------------------------------------------------------------
__global__ __launch_bounds__(512) void squash_kernel(float* __restrict__ out,
                                                     int last, int first)
{
    const int t = threadIdx.x;
    const int TOT = NB * NC * NO;

    float sv[32];
    float acc = 0.f;
#pragma unroll
    for (int q = 0; q < 32; q++) {
        int j = t + 512 * q;
        float s;
        if (first) {
            s = g_pnum[j] * (1.0f / (float)NR);
        } else {
            float D = g_pden[j] + g_pden[TOT + j];
            float N = g_pnum[j] + g_pnum[TOT + j];
            s = N / D;
        }
        sv[q] = s;
        acc += s * s;
    }

    __shared__ float red[16];
    __shared__ float s_scale;
#pragma unroll
    for (int off = 16; off > 0; off >>= 1)
        acc += __shfl_xor_sync(0xFFFFFFFFu, acc, off);
    if ((t & 31) == 0) red[t >> 5] = acc;
    __syncthreads();
    if (t < 32) {
        float a = (t < 16) ? red[t] : 0.f;
#pragma unroll
        for (int off = 8; off > 0; off >>= 1)
            a += __shfl_xor_sync(0xFFFFFFFFu, a, off);
        if (t == 0) s_scale = sqrtf(a) / (1.0f + a);
    }
    __syncthreads();
    const float sc = s_scale;

    if (last) {
#pragma unroll
        for (int q = 0; q < 32; q++) out[t + 512 * q] = sv[q] * sc;
    } else {
#pragma unroll
        for (int q = 0; q < 32; q++) g_w[t + 512 * q] += sv[q] * sc;
    }
}

// ---------------------------------------------------------------------------
extern "C" void kernel_launch(void* const* d_in, const int* in_sizes, int n_in,
                              void* d_out, int out_size)
{
    (void)in_sizes; (void)n_in; (void)out_size;
    const float* x  = (const float*)d_in[0];
    const float* Wt = (const float*)d_in[1];
    float* out = (float*)d_out;

    cudaFuncSetAttribute(priors_kernel,
                         cudaFuncAttributeMaxDynamicSharedMemorySize, SMEM_TOTAL);

    zero_kernel<<<64, 512>>>();
    priors_kernel<<<dim3(NR / RT, NC), 128, SMEM_TOTAL>>>(x, Wt);

    squash_kernel<<<1, 512>>>(nullptr, 0, 1);   // w = v0   (iteration 0, fused sum)

    iter_kernel<<<2 * NB * NC, 512>>>();        // iteration 1
    squash_kernel<<<1, 512>>>(nullptr, 0, 0);   // w = v0 + v1

    iter_kernel<<<2 * NB * NC, 512>>>();        // iteration 2
    squash_kernel<<<1, 512>>>(out, 1, 0);       // final squash -> output
}

// round 8
// speedup vs baseline: 1.2458x; 1.0164x over previous
#include <cuda_runtime.h>
#include <cuda_fp16.h>
#include <cstdint>
#include <math.h>

#define NB 8
#define NC 32
#define NR 2048
#define NI 64
#define NO 64
#define RT 16                 // r-values per priors block
#define RS 2                  // r-values per pipeline stage (32 KB W slab)
#define NSTAGE (RT / RS)      // 8
#define NQ 4                  // R-split quarters in iter_kernel

// dynamic smem layout (bytes): W 2x32KB | x 2x4KB | mbar
#define SMEM_W     0
#define SMEM_X     65536
#define SMEM_MBAR  73728
#define SMEM_TOTAL 73760

#define TOT (NB * NC * NO)    // 16384

// Scratch (static device globals — no allocation in kernel_launch)
__device__ __half g_ph[NB * NC * NR * NO];      // 67 MB fp16 priors -> L2 resident
__device__ float  g_w[TOT];                     // cumulative v (logit weight)
__device__ float  g_pden[NQ * TOT];             // per-quarter softmax denominators
__device__ float  g_pnum[NQ * TOT];             // per-quarter numerators; [0] also = sum_r priors

// ---------------------------------------------------------------------------
__device__ __forceinline__ unsigned sptr(const void* p) {
    return (unsigned)__cvta_generic_to_shared(p);
}
__device__ __forceinline__ void mbar_init(unsigned m, unsigned cnt) {
    asm volatile("mbarrier.init.shared.b64 [%0], %1;" :: "r"(m), "r"(cnt) : "memory");
}
__device__ __forceinline__ void mbar_expect(unsigned m, unsigned bytes) {
    asm volatile("mbarrier.arrive.expect_tx.shared.b64 _, [%0], %1;"
                 :: "r"(m), "r"(bytes) : "memory");
}
__device__ __forceinline__ void bulk_g2s(unsigned dst, const void* src,
                                         unsigned bytes, unsigned m) {
    asm volatile("cp.async.bulk.shared::cta.global.mbarrier::complete_tx::bytes "
                 "[%0], [%1], %2, [%3];"
                 :: "r"(dst), "l"(src), "r"(bytes), "r"(m) : "memory");
}
__device__ __forceinline__ void mbar_wait(unsigned m, unsigned ph) {
    asm volatile(
        "{\n\t.reg .pred P;\n\t"
        "W1_%=:\n\t"
        "mbarrier.try_wait.parity.acquire.cta.shared::cta.b64 P, [%0], %1, 0x989680;\n\t"
        "@P bra W2_%=;\n\t"
        "bra W1_%=;\n\t"
        "W2_%=:\n\t}"
        :: "r"(m), "r"(ph) : "memory");
}

#define FMA4(A, S, W) { (A).x += (S)*(W).x; (A).y += (S)*(W).y; \
                        (A).z += (S)*(W).z; (A).w += (S)*(W).w; }

// ---------------------------------------------------------------------------
// Kernel 0: zero the accumulators (g_w and quarter-0 of g_pnum).
// ---------------------------------------------------------------------------
__global__ __launch_bounds__(512) void zero_kernel()
{
    int i = blockIdx.x * 512 + threadIdx.x;
    if (i < TOT) { g_w[i] = 0.0f; g_pnum[i] = 0.0f; }
}

// ---------------------------------------------------------------------------
// Kernel 1: priors[b,c,r,o] = sum_i x[b,c,r,i] * W[c,r,i,o], fp16 store.
// TMA bulk double-buffered pipeline; W (32 KB) and x (4 KB) per stage.
// smem = 72 KB -> 3 blocks/SM (12 warps) for stall coverage.
// Fuses iteration-0 sum (w=0 -> uniform softmax -> mean) via atomics.
// Block: 128 threads = (rj 0..1) x (bq 0..3) x (og 0..15); thread computes
// 2 batches (2bq, 2bq+1) x 4 outputs for r = r0 + RS*s + rj.
// ---------------------------------------------------------------------------
__global__ __launch_bounds__(128) void priors_kernel(
    const float* __restrict__ x, const float* __restrict__ Wt)
{
    extern __shared__ float sm[];
    float* sW = sm;                          // [2][RS*NI*NO]
    float* sX = sm + SMEM_X / 4;             // [2][NB][RS*NI]
    const unsigned smb = sptr(sm);
    const unsigned mb0 = smb + SMEM_MBAR;
    const unsigned mb1 = mb0 + 8;

    const int c  = blockIdx.y;
    const int r0 = blockIdx.x * RT;
    const int t  = threadIdx.x;
    const int rj = t >> 6;
    const int bq = (t >> 4) & 3;
    const int og = t & 15;
    const int b0 = 2 * bq, b1 = 2 * bq + 1;

    if (t == 0) { mbar_init(mb0, 1); mbar_init(mb1, 1); }
    __syncthreads();

    // stage loader: 32 KB W slab + 8 x-rows (512 B each)
    auto load_stage = [&](int s, int buf, unsigned m) {
        mbar_expect(m, 32768 + NB * RS * NI * 4);
        bulk_g2s(smb + SMEM_W + buf * 32768,
                 Wt + (size_t)(c * NR + r0 + s * RS) * (NI * NO), 32768, m);
#pragma unroll
        for (int b = 0; b < NB; b++)
            bulk_g2s(smb + SMEM_X + buf * (NB * RS * NI * 4) + b * (RS * NI * 4),
                     x + (size_t)((b * NC + c) * NR + r0 + s * RS) * NI,
                     RS * NI * 4, m);
    };

    if (t == 0) load_stage(0, 0, mb0);

    unsigned ph0 = 0, ph1 = 0;
    float4 ms0 = make_float4(0.f, 0.f, 0.f, 0.f);
    float4 ms1 = make_float4(0.f, 0.f, 0.f, 0.f);

    for (int s = 0; s < NSTAGE; s++) {
        const int buf = s & 1;

        // prefetch next stage (other buffer was freed by syncthreads at s-1 end)
        if (t == 0 && s + 1 < NSTAGE)
            load_stage(s + 1, (s + 1) & 1, ((s + 1) & 1) ? mb1 : mb0);

        if (buf == 0) { mbar_wait(mb0, ph0); ph0 ^= 1; }
        else          { mbar_wait(mb1, ph1); ph1 ^= 1; }

        const float*  Wb  = sW + buf * (RS * NI * NO) + rj * (NI * NO);
        const float4* xr0 = (const float4*)(sX + buf * (NB * RS * NI) + (b0 * RS + rj) * NI);
        const float4* xr1 = (const float4*)(sX + buf * (NB * RS * NI) + (b1 * RS + rj) * NI);

        float4 a0 = make_float4(0.f, 0.f, 0.f, 0.f);
        float4 a1 = make_float4(0.f, 0.f, 0.f, 0.f);

#pragma unroll
        for (int i4 = 0; i4 < NI / 4; i4++) {
            float4 xv0 = xr0[i4];
            float4 xv1 = xr1[i4];
            const float4* wrow = (const float4*)(Wb + (i4 * 4) * NO) + og;
            float4 w0 = wrow[0];
            float4 w1 = wrow[16];
            float4 w2 = wrow[32];
            float4 w3 = wrow[48];
            FMA4(a0, xv0.x, w0); FMA4(a1, xv1.x, w0);
            FMA4(a0, xv0.y, w1); FMA4(a1, xv1.y, w1);
            FMA4(a0, xv0.z, w2); FMA4(a1, xv1.z, w2);
            FMA4(a0, xv0.w, w3); FMA4(a1, xv1.w, w3);
        }

        const int r = r0 + s * RS + rj;
        {
            union { uint2 u; __half2 h[2]; } pk;
            pk.h[0] = __floats2half2_rn(a0.x, a0.y);
            pk.h[1] = __floats2half2_rn(a0.z, a0.w);
            *(uint2*)(g_ph + (size_t)((b0 * NC + c) * NR + r) * NO + 4 * og) = pk.u;
            pk.h[0] = __floats2half2_rn(a1.x, a1.y);
            pk.h[1] = __floats2half2_rn(a1.z, a1.w);
            *(uint2*)(g_ph + (size_t)((b1 * NC + c) * NR + r) * NO + 4 * og) = pk.u;
        }

        ms0.x += a0.x; ms0.y += a0.y; ms0.z += a0.z; ms0.w += a0.w;
        ms1.x += a1.x; ms1.y += a1.y; ms1.z += a1.z; ms1.w += a1.w;

        __syncthreads();     // stage buffers free for reuse
    }

    // iteration-0 fusion: sum_r priors -> g_pnum quarter 0
    float* d0 = g_pnum + (b0 * NC + c) * NO + 4 * og;
    float* d1 = g_pnum + (b1 * NC + c) * NO + 4 * og;
    atomicAdd(d0 + 0, ms0.x); atomicAdd(d0 + 1, ms0.y);
    atomicAdd(d0 + 2, ms0.z); atomicAdd(d0 + 3, ms0.w);
    atomicAdd(d1 + 0, ms1.x); atomicAdd(d1 + 1, ms1.y);
    atomicAdd(d1 + 2, ms1.z); atomicAdd(d1 + 3, ms1.w);
}

// ---------------------------------------------------------------------------
// Kernel 2: one routing iteration (branch-free: |w|<=2, |p|<~16 -> exp safe).
// Grid = NQ blocks per (b,c), 512 rows each; partials to scratch quarters.
// ---------------------------------------------------------------------------
__global__ __launch_bounds__(512) void iter_kernel()
{
    const int blk = blockIdx.x;
    const int bc  = blk >> 2;
    const int qq  = blk & 3;
    const int t   = threadIdx.x;
    const int o4  = t & 15;
    const int g   = t >> 4;

    const uint2* p2 = (const uint2*)(g_ph + (size_t)bc * NR * NO)
                      + (size_t)qq * (NR / NQ) * 16;
    const float4 wv = ((const float4*)g_w)[bc * 16 + o4];

    float d0 = 0.f, d1 = 0.f, d2 = 0.f, d3 = 0.f;
    float n0 = 0.f, n1 = 0.f, n2 = 0.f, n3 = 0.f;

#pragma unroll
    for (int k = 0; k < NR / NQ / 32; k++) {      // 16
        uint2 u = p2[(size_t)(g + 32 * k) * 16 + o4];
        float2 pa = __half22float2(*(__half2*)&u.x);
        float2 pb = __half22float2(*(__half2*)&u.y);
        float e;
        e = __expf(pa.x * wv.x); d0 += e; n0 += pa.x * e;
        e = __expf(pa.y * wv.y); d1 += e; n1 += pa.y * e;
        e = __expf(pb.x * wv.z); d2 += e; n2 += pb.x * e;
        e = __expf(pb.y * wv.w); d3 += e; n3 += pb.y * e;
    }

    __shared__ float smr[2][32][64];
    {
        int ob = o4 * 4;
        smr[0][g][ob + 0] = d0; smr[1][g][ob + 0] = n0;
        smr[0][g][ob + 1] = d1; smr[1][g][ob + 1] = n1;
        smr[0][g][ob + 2] = d2; smr[1][g][ob + 2] = n2;
        smr[0][g][ob + 3] = d3; smr[1][g][ob + 3] = n3;
    }
    __syncthreads();

    if (t < 64) {
        float D = 0.f, N = 0.f;
#pragma unroll 8
        for (int g2 = 0; g2 < 32; g2++) {
            D += smr[0][g2][t];
            N += smr[1][g2][t];
        }
        g_pden[qq * TOT + bc * NO + t] = D;
        g_pnum[qq * TOT + bc * NO + t] = N;
    }
}

// ---------------------------------------------------------------------------
// Kernel 3: s -> squash scale -> update w or write out.
// first=1: s = g_pnum[0]/2048 (uniform softmax, fused iteration 0).
// ---------------------------------------------------------------------------
__global__ __launch_bounds__(512) void squash_kernel(float* __restrict__ out,
                                                     int last, int first)
{
    const int t = threadIdx.x;

    float sv[32];
    float acc = 0.f;
#pragma unroll
    for (int q = 0; q < 32; q++) {
        int j = t + 512 * q;
        float s;
        if (first) {
            s = g_pnum[j] * (1.0f / (float)NR);
        } else {
            float D = g_pden[j] + g_pden[TOT + j] + g_pden[2 * TOT + j] + g_pden[3 * TOT + j];
            float N = g_pnum[j] + g_pnum[TOT + j] + g_pnum[2 * TOT + j] + g_pnum[3 * TOT + j];
            s = N / D;
        }
        sv[q] = s;
        acc += s * s;
    }

    __shared__ float red[16];
    __shared__ float s_scale;
#pragma unroll
    for (int off = 16; off > 0; off >>= 1)
        acc += __shfl_xor_sync(0xFFFFFFFFu, acc, off);
    if ((t & 31) == 0) red[t >> 5] = acc;
    __syncthreads();
    if (t < 32) {
        float a = (t < 16) ? red[t] : 0.f;
#pragma unroll
        for (int off = 8; off > 0; off >>= 1)
            a += __shfl_xor_sync(0xFFFFFFFFu, a, off);
        if (t == 0) s_scale = sqrtf(a) / (1.0f + a);
    }
    __syncthreads();
    const float sc = s_scale;

    if (last) {
#pragma unroll
        for (int q = 0; q < 32; q++) out[t + 512 * q] = sv[q] * sc;
    } else {
#pragma unroll
        for (int q = 0; q < 32; q++) g_w[t + 512 * q] += sv[q] * sc;
    }
}

// ---------------------------------------------------------------------------
extern "C" void kernel_launch(void* const* d_in, const int* in_sizes, int n_in,
                              void* d_out, int out_size)
{
    (void)in_sizes; (void)n_in; (void)out_size;
    const float* x  = (const float*)d_in[0];
    const float* Wt = (const float*)d_in[1];
    float* out = (float*)d_out;

    cudaFuncSetAttribute(priors_kernel,
                         cudaFuncAttributeMaxDynamicSharedMemorySize, SMEM_TOTAL);

    zero_kernel<<<32, 512>>>();
    priors_kernel<<<dim3(NR / RT, NC), 128, SMEM_TOTAL>>>(x, Wt);

    squash_kernel<<<1, 512>>>(nullptr, 0, 1);   // w = v0   (iteration 0, fused sum)

    iter_kernel<<<NQ * NB * NC, 512>>>();       // iteration 1
    squash_kernel<<<1, 512>>>(nullptr, 0, 0);   // w = v0 + v1

    iter_kernel<<<NQ * NB * NC, 512>>>();       // iteration 2
    squash_kernel<<<1, 512>>>(out, 1, 0);       // final squash -> output
}